// round 4
// baseline (speedup 1.0000x reference)
#include <cuda_runtime.h>
#include <cuda_bf16.h>
#include <cstdint>
#include <cstddef>

// ----------------------------------------------------------------------------
// Problem constants
// ----------------------------------------------------------------------------
#define BB   512
#define QQ   32768
#define DD   256
#define ROWL 32769            // 1 + Q
#define NCOMBO 8

__constant__ int d_CI[8] = {0, 0, 0, 1, 1, 2, 2, 3};
__constant__ int d_CJ[8] = {1, 2, 3, 0, 2, 0, 1, 0};

// ----------------------------------------------------------------------------
// Scratch (device globals; no allocation allowed)
// Quantized rows: v ~= s * (128*h + l), h,l int8, s = rowAbsMax/16256.
// Stored packed, 8 bytes per lane slot: [4][rows][32] uint2 (row = 256 bytes).
// ----------------------------------------------------------------------------
__device__ __align__(16) uint2 g_mq_h[4u * QQ * 32];   // 33.5 MB
__device__ __align__(16) uint2 g_mq_l[4u * QQ * 32];   // 33.5 MB
__device__ __align__(16) uint2 g_xq_h[4 * BB * 32];
__device__ __align__(16) uint2 g_xq_l[4 * BB * 32];
__device__ float g_ms[4 * QQ];        // mem row quant scales (sb)
__device__ float g_xs[4 * BB];        // x row quant scales (sa)
__device__ float g_norm[4 * BB];
__device__ float g_scale2[NCOMBO * BB];   // sa * 1/(ni*nj*T) per (combo,row)

// ----------------------------------------------------------------------------
// PTX helpers (sm_103-safe: mma.sync / ldmatrix / cp.async only)
// ----------------------------------------------------------------------------
__device__ __forceinline__ uint32_t smem_to_u32(const void* p) {
    uint32_t a;
    asm("{ .reg .u64 t; cvta.to.shared.u64 t, %1; cvt.u32.u64 %0, t; }" : "=r"(a) : "l"(p));
    return a;
}

__device__ __forceinline__ void cp_async16(uint32_t saddr, const void* gaddr) {
    asm volatile("cp.async.cg.shared.global [%0], [%1], 16;" :: "r"(saddr), "l"(gaddr));
}
__device__ __forceinline__ void cp_commit() {
    asm volatile("cp.async.commit_group;" ::: "memory");
}
template <int N>
__device__ __forceinline__ void cp_wait() {
    asm volatile("cp.async.wait_group %0;" :: "n"(N) : "memory");
}

__device__ __forceinline__ void ldsm_x4(uint32_t* r, uint32_t addr) {
    asm volatile("ldmatrix.sync.aligned.m8n8.x4.shared.b16 {%0,%1,%2,%3}, [%4];"
                 : "=r"(r[0]), "=r"(r[1]), "=r"(r[2]), "=r"(r[3]) : "r"(addr));
}

// s8 MMA: m16n8k32, s32 accumulate (exact)
__device__ __forceinline__ void mma_s8(int* d, const uint32_t* a, const uint32_t* b) {
    asm volatile(
        "mma.sync.aligned.m16n8k32.row.col.s32.s8.s8.s32 "
        "{%0,%1,%2,%3}, {%4,%5,%6,%7}, {%8,%9}, {%0,%1,%2,%3};"
        : "+r"(d[0]), "+r"(d[1]), "+r"(d[2]), "+r"(d[3])
        : "r"(a[0]), "r"(a[1]), "r"(a[2]), "r"(a[3]), "r"(b[0]), "r"(b[1]));
}

// ----------------------------------------------------------------------------
// Small helpers
// ----------------------------------------------------------------------------
__device__ __forceinline__ const float* sel4(int v, const float* a, const float* b,
                                             const float* c, const float* d) {
    return v == 0 ? a : (v == 1 ? b : (v == 2 ? c : d));
}

__device__ __forceinline__ uint32_t pack4(int a, int b, int c, int d) {
    return (uint32_t)(a & 255) | ((uint32_t)(b & 255) << 8) |
           ((uint32_t)(c & 255) << 16) | ((uint32_t)(d & 255) << 24);
}

// quantize one float given inv scale: returns h,l ints
__device__ __forceinline__ void quant1(float v, float inv, int& ih, int& il) {
    float q = v * inv;                       // |q| <= 16256
    float fh = rintf(q * 0.0078125f);        // q/128, in [-127,127]
    float fl = rintf(fmaf(-128.f, fh, q));   // in [-64,64]
    ih = (int)fh; il = (int)fl;
}

// warp-level quantize of one 256-float row into packed h/l uint2 slots
__device__ __forceinline__ void quant_row(const float* row, int lane,
                                          uint2* dst_h, uint2* dst_l, float* s_out) {
    float4 f0 = *reinterpret_cast<const float4*>(row + lane * 8);
    float4 f1 = *reinterpret_cast<const float4*>(row + lane * 8 + 4);
    float m = fmaxf(fmaxf(fmaxf(fabsf(f0.x), fabsf(f0.y)), fmaxf(fabsf(f0.z), fabsf(f0.w))),
                    fmaxf(fmaxf(fabsf(f1.x), fabsf(f1.y)), fmaxf(fabsf(f1.z), fabsf(f1.w))));
#pragma unroll
    for (int o = 16; o; o >>= 1) m = fmaxf(m, __shfl_xor_sync(0xffffffffu, m, o));
    m = fmaxf(m, 1e-30f);
    float inv = 16256.f / m;
    int h[8], l[8];
    quant1(f0.x, inv, h[0], l[0]); quant1(f0.y, inv, h[1], l[1]);
    quant1(f0.z, inv, h[2], l[2]); quant1(f0.w, inv, h[3], l[3]);
    quant1(f1.x, inv, h[4], l[4]); quant1(f1.y, inv, h[5], l[5]);
    quant1(f1.z, inv, h[6], l[6]); quant1(f1.w, inv, h[7], l[7]);
    uint2 ph, pl;
    ph.x = pack4(h[0], h[1], h[2], h[3]); ph.y = pack4(h[4], h[5], h[6], h[7]);
    pl.x = pack4(l[0], l[1], l[2], l[3]); pl.y = pack4(l[4], l[5], l[6], l[7]);
    dst_h[lane] = ph;
    dst_l[lane] = pl;
    if (lane == 0) *s_out = m * (1.f / 16256.f);
}

// ----------------------------------------------------------------------------
// k_norm: per-row L2 norms of the 4 X views (one warp per row)
// ----------------------------------------------------------------------------
__global__ void k_norm(const float* __restrict__ x0, const float* __restrict__ x1,
                       const float* __restrict__ x2, const float* __restrict__ x3) {
    int gw = (blockIdx.x * blockDim.x + threadIdx.x) >> 5;
    int lane = threadIdx.x & 31;
    if (gw >= 4 * BB) return;
    int v = gw >> 9, b = gw & (BB - 1);
    const float* row = sel4(v, x0, x1, x2, x3) + (size_t)b * DD;
    float s = 0.f;
#pragma unroll
    for (int k = 0; k < 8; k++) { float t = row[lane + k * 32]; s += t * t; }
#pragma unroll
    for (int o = 16; o; o >>= 1) s += __shfl_xor_sync(0xffffffffu, s, o);
    if (lane == 0) g_norm[gw] = sqrtf(s);
}

// ----------------------------------------------------------------------------
// k_prep_x: X -> quantized h/l scratch (warp per row); Y -> tail of new_mem.
// grid (64 + 128, 4), 256 threads
// ----------------------------------------------------------------------------
__global__ void k_prep_x(const float* __restrict__ x0, const float* __restrict__ x1,
                         const float* __restrict__ x2, const float* __restrict__ x3,
                         const float* __restrict__ y0, const float* __restrict__ y1,
                         const float* __restrict__ y2, const float* __restrict__ y3,
                         float* __restrict__ out_mem) {
    int v = blockIdx.y;
    int bx = blockIdx.x;
    int t = threadIdx.x;
    if (bx < 64) {
        int wid = t >> 5, lane = t & 31;
        int row = bx * 8 + wid;                       // < 512
        const float* rp = sel4(v, x0, x1, x2, x3) + (size_t)row * DD;
        size_t slot = ((size_t)v * BB + row) * 32;
        quant_row(rp, lane, g_xq_h + slot, g_xq_l + slot, g_xs + v * BB + row);
    } else {
        int idx = (bx - 64) * 256 + t;                // < 32768 float4 per view
        float4 f = reinterpret_cast<const float4*>(sel4(v, y0, y1, y2, y3))[idx];
        reinterpret_cast<float4*>(out_mem)[(size_t)v * (QQ * DD / 4) + (size_t)(QQ - BB) * (DD / 4) + idx] = f;
    }
}

// ----------------------------------------------------------------------------
// k_self: self-dots (column 0, full fp32) + combined per-row scales.
// ----------------------------------------------------------------------------
__global__ void k_self(const float* __restrict__ x0, const float* __restrict__ x1,
                       const float* __restrict__ x2, const float* __restrict__ x3,
                       float* __restrict__ out) {
    int gw = (blockIdx.x * blockDim.x + threadIdx.x) >> 5;
    int lane = threadIdx.x & 31;
    if (gw >= NCOMBO * BB) return;
    int c = gw >> 9, b = gw & (BB - 1);
    int i = d_CI[c], j = d_CJ[c];
    const float* xi = sel4(i, x0, x1, x2, x3) + (size_t)b * DD;
    const float* xj = sel4(j, x0, x1, x2, x3) + (size_t)b * DD;
    float s = 0.f;
#pragma unroll
    for (int k = 0; k < 8; k++) s += xi[lane + k * 32] * xj[lane + k * 32];
#pragma unroll
    for (int o = 16; o; o >>= 1) s += __shfl_xor_sync(0xffffffffu, s, o);
    if (lane == 0) {
        float sc = 1.0f / (g_norm[i * BB + b] * g_norm[j * BB + b] * 0.07f);
        g_scale2[c * BB + b] = sc * g_xs[i * BB + b];   // fold in sa
        out[(size_t)c * BB * ROWL + (size_t)b * ROWL] = __expf(s * sc);
    }
}

// ----------------------------------------------------------------------------
// k_prep_mem: Mem -> quantized h/l scratch AND FIFO-shifted new_mem output.
// One warp per row; grid (4096, 4), 256 threads.
// ----------------------------------------------------------------------------
__global__ void k_prep_mem(const float* __restrict__ m0, const float* __restrict__ m1,
                           const float* __restrict__ m2, const float* __restrict__ m3,
                           float* __restrict__ out_mem) {
    int v = blockIdx.y;
    int wid = threadIdx.x >> 5, lane = threadIdx.x & 31;
    int row = blockIdx.x * 8 + wid;                   // < 32768
    const float* rp = sel4(v, m0, m1, m2, m3) + (size_t)row * DD;

    float4 f0 = *reinterpret_cast<const float4*>(rp + lane * 8);
    float4 f1 = *reinterpret_cast<const float4*>(rp + lane * 8 + 4);
    float m = fmaxf(fmaxf(fmaxf(fabsf(f0.x), fabsf(f0.y)), fmaxf(fabsf(f0.z), fabsf(f0.w))),
                    fmaxf(fmaxf(fabsf(f1.x), fabsf(f1.y)), fmaxf(fabsf(f1.z), fabsf(f1.w))));
#pragma unroll
    for (int o = 16; o; o >>= 1) m = fmaxf(m, __shfl_xor_sync(0xffffffffu, m, o));
    m = fmaxf(m, 1e-30f);
    float inv = 16256.f / m;
    int h[8], l[8];
    quant1(f0.x, inv, h[0], l[0]); quant1(f0.y, inv, h[1], l[1]);
    quant1(f0.z, inv, h[2], l[2]); quant1(f0.w, inv, h[3], l[3]);
    quant1(f1.x, inv, h[4], l[4]); quant1(f1.y, inv, h[5], l[5]);
    quant1(f1.z, inv, h[6], l[6]); quant1(f1.w, inv, h[7], l[7]);
    uint2 ph, pl;
    ph.x = pack4(h[0], h[1], h[2], h[3]); ph.y = pack4(h[4], h[5], h[6], h[7]);
    pl.x = pack4(l[0], l[1], l[2], l[3]); pl.y = pack4(l[4], l[5], l[6], l[7]);
    size_t slot = ((size_t)v * QQ + row) * 32 + lane;
    g_mq_h[slot] = ph;
    g_mq_l[slot] = pl;
    if (lane == 0) g_ms[v * QQ + row] = m * (1.f / 16256.f);

    // FIFO shift: rows [B, Q) of mem become rows [0, Q-B) of new_mem
    if (row >= BB) {
        float* dst = out_mem + ((size_t)v * QQ + row - BB) * DD;
        *reinterpret_cast<float4*>(dst + lane * 8) = f0;
        *reinterpret_cast<float4*>(dst + lane * 8 + 4) = f1;
    }
}

// ----------------------------------------------------------------------------
// k_gemm: s8 fixed-point split GEMM via mma.sync m16n8k32 + exp epilogue.
// Block tile M=128 x N=128, K=256 int8 in 2 chunks of 128 (both prefetched).
// 8 warps: 2 (m) x 4 (n); warp tile 64x32.
// Smem tiles: 128 rows x 128 bytes, padded row stride 144 B.
// dot = sa*sb*(16384*hh + 128*(hl+lh))   [ll dropped, ~2^-14 relative]
// ----------------------------------------------------------------------------
#define TS_ROWB   144
#define TILE_B    (128 * TS_ROWB)          // 18432
#define BUF_B     (4 * TILE_B)             // 73728 (Ah, Al, Bh, Bl)
#define OFF_TILES 512                      // sbn[128] floats first
#define GEMM_SMEM (OFF_TILES + 2 * BUF_B)  // 147968

__global__ void __launch_bounds__(256) k_gemm(float* __restrict__ out) {
    extern __shared__ char smem[];
    const uint32_t sb = smem_to_u32(smem);
    float* sbn = reinterpret_cast<float*>(smem);
    const int tid = threadIdx.x, lane = tid & 31, wid = tid >> 5;
    const int wm = wid & 1, wn = wid >> 1;
    const int cm = blockIdx.x;
    const int c = cm >> 2, mtile = cm & 3, ntile = blockIdx.y;
    const int i = d_CI[c], j = d_CJ[c];

    const char* src[4];
    src[0] = reinterpret_cast<const char*>(g_xq_h) + ((size_t)i * BB + mtile * 128) * 256;
    src[1] = reinterpret_cast<const char*>(g_xq_l) + ((size_t)i * BB + mtile * 128) * 256;
    src[2] = reinterpret_cast<const char*>(g_mq_h) + ((size_t)j * QQ + (size_t)ntile * 128) * 256;
    src[3] = reinterpret_cast<const char*>(g_mq_l) + ((size_t)j * QQ + (size_t)ntile * 128) * 256;

    // stage sb column scales (128 floats)
    if (tid < 128) sbn[tid] = g_ms[(size_t)j * QQ + ntile * 128 + tid];

    // per-thread load slots: 4 uint4 per tile (1024 units of 16B per tile)
    const int l_row[4] = { (tid + 0 * 256) >> 3, (tid + 1 * 256) >> 3,
                           (tid + 2 * 256) >> 3, (tid + 3 * 256) >> 3 };
    const int l_seg = tid & 7;

    auto issue_chunk = [&](int kc, int buf) {
        uint32_t sbase = sb + OFF_TILES + buf * BUF_B;
#pragma unroll
        for (int t = 0; t < 4; t++) {
#pragma unroll
            for (int r = 0; r < 4; r++) {
                const char* g = src[t] + (size_t)l_row[r] * 256 + kc * 128 + l_seg * 16;
                uint32_t s = sbase + t * TILE_B + l_row[r] * TS_ROWB + l_seg * 16;
                cp_async16(s, g);
            }
        }
        cp_commit();
    };

    int acc_hh[4][4][4], acc_md[4][4][4];
#pragma unroll
    for (int a = 0; a < 4; a++)
#pragma unroll
        for (int b = 0; b < 4; b++)
#pragma unroll
            for (int k = 0; k < 4; k++) { acc_hh[a][b][k] = 0; acc_md[a][b][k] = 0; }

    // ldmatrix base offsets (within a buffer); 32-byte k-steps, 16B sub-chunks
    const uint32_t a_lane_off = (uint32_t)((lane & 15) * TS_ROWB + (lane >> 4) * 16);
    const uint32_t b_lane_off = (uint32_t)(((lane & 7) + ((lane >> 4) << 3)) * TS_ROWB
                                           + (((lane >> 3) & 1) * 16));

    issue_chunk(0, 0);
    issue_chunk(1, 1);

    auto compute = [&](uint32_t bufb) {
        const uint32_t aH = bufb + 0 * TILE_B + (wm * 64) * TS_ROWB + a_lane_off;
        const uint32_t aL = bufb + 1 * TILE_B + (wm * 64) * TS_ROWB + a_lane_off;
        const uint32_t bH = bufb + 2 * TILE_B + (wn * 32) * TS_ROWB + b_lane_off;
        const uint32_t bL = bufb + 3 * TILE_B + (wn * 32) * TS_ROWB + b_lane_off;
#pragma unroll
        for (int step = 0; step < 4; step++) {
            const uint32_t koff = step * 32;   // 32 int8 = 32 bytes
            uint32_t bh[8], bl[8];
            ldsm_x4(bh + 0, bH + koff);                       // n 0-15
            ldsm_x4(bh + 4, bH + 16 * TS_ROWB + koff);        // n 16-31
            ldsm_x4(bl + 0, bL + koff);
            ldsm_x4(bl + 4, bL + 16 * TS_ROWB + koff);
#pragma unroll
            for (int mi = 0; mi < 4; mi++) {
                uint32_t ah[4], al[4];
                ldsm_x4(ah, aH + mi * 16 * TS_ROWB + koff);
                ldsm_x4(al, aL + mi * 16 * TS_ROWB + koff);
#pragma unroll
                for (int ni = 0; ni < 4; ni++) {
                    mma_s8(acc_hh[mi][ni], ah, bh + ni * 2);
                    mma_s8(acc_md[mi][ni], ah, bl + ni * 2);
                    mma_s8(acc_md[mi][ni], al, bh + ni * 2);
                }
            }
        }
    };

    cp_wait<1>();
    __syncthreads();
    compute(sb + OFF_TILES + 0 * BUF_B);
    cp_wait<0>();
    __syncthreads();
    compute(sb + OFF_TILES + 1 * BUF_B);

    // Epilogue: exp((16384*hh + 128*mid) * sa_scale * sb) -> out
    const int r0 = lane >> 2;
    const int cpair = (lane & 3) * 2;
#pragma unroll
    for (int mi = 0; mi < 4; mi++) {
        const int grow0 = mtile * 128 + wm * 64 + mi * 16 + r0;
        const float scl0 = g_scale2[c * BB + grow0];
        const float scl1 = g_scale2[c * BB + grow0 + 8];
        const size_t base0 = ((size_t)c * BB + grow0) * ROWL;
        const size_t base1 = base0 + (size_t)8 * ROWL;
#pragma unroll
        for (int ni = 0; ni < 4; ni++) {
            const int colL = wn * 32 + ni * 8 + cpair;
            const float sb0 = sbn[colL], sb1 = sbn[colL + 1];
            const size_t col = 1 + (size_t)ntile * 128 + colL;
            float d0 = fmaf(16384.f, (float)acc_hh[mi][ni][0], 128.f * (float)acc_md[mi][ni][0]);
            float d1 = fmaf(16384.f, (float)acc_hh[mi][ni][1], 128.f * (float)acc_md[mi][ni][1]);
            float d2 = fmaf(16384.f, (float)acc_hh[mi][ni][2], 128.f * (float)acc_md[mi][ni][2]);
            float d3 = fmaf(16384.f, (float)acc_hh[mi][ni][3], 128.f * (float)acc_md[mi][ni][3]);
            out[base0 + col + 0] = __expf(d0 * (scl0 * sb0));
            out[base0 + col + 1] = __expf(d1 * (scl0 * sb1));
            out[base1 + col + 0] = __expf(d2 * (scl1 * sb0));
            out[base1 + col + 1] = __expf(d3 * (scl1 * sb1));
        }
    }
}

// ----------------------------------------------------------------------------
// kernel_launch — input order detected from in_sizes (interleaved vs grouped)
// ----------------------------------------------------------------------------
extern "C" void kernel_launch(void* const* d_in, const int* in_sizes, int n_in,
                              void* d_out, int out_size) {
    (void)n_in; (void)out_size;
    const float* x[4]; const float* y[4]; const float* m[4];
    const bool interleaved = (in_sizes[2] == QQ * DD);
    for (int v = 0; v < 4; v++) {
        if (interleaved) {
            x[v] = (const float*)d_in[3 * v + 0];
            y[v] = (const float*)d_in[3 * v + 1];
            m[v] = (const float*)d_in[3 * v + 2];
        } else {
            x[v] = (const float*)d_in[v];
            y[v] = (const float*)d_in[4 + v];
            m[v] = (const float*)d_in[8 + v];
        }
    }
    float* out = (float*)d_out;
    float* out_mem = out + (size_t)NCOMBO * BB * ROWL;

    cudaFuncSetAttribute(k_gemm, cudaFuncAttributeMaxDynamicSharedMemorySize, GEMM_SMEM);

    k_norm<<<256, 256>>>(x[0], x[1], x[2], x[3]);
    k_prep_x<<<dim3(192, 4), 256>>>(x[0], x[1], x[2], x[3],
                                    y[0], y[1], y[2], y[3], out_mem);
    k_self<<<512, 256>>>(x[0], x[1], x[2], x[3], out);
    k_prep_mem<<<dim3(4096, 4), 256>>>(m[0], m[1], m[2], m[3], out_mem);
    k_gemm<<<dim3(32, 256), 256, GEMM_SMEM>>>(out);
}

// round 6
// speedup vs baseline: 3.7384x; 3.7384x over previous
#include <cuda_runtime.h>
#include <cuda_fp16.h>
#include <cstdint>
#include <cstddef>

// ----------------------------------------------------------------------------
// Problem constants
// ----------------------------------------------------------------------------
#define BB   512
#define QQ   32768
#define DD   256
#define ROWL 32769            // 1 + Q
#define NCOMBO 8

__constant__ int d_CI[8] = {0, 0, 0, 1, 1, 2, 2, 3};
__constant__ int d_CJ[8] = {1, 2, 3, 0, 2, 0, 1, 0};

// ----------------------------------------------------------------------------
// Scratch (device globals; no allocation allowed)
// ----------------------------------------------------------------------------
__device__ __align__(16) __half g_m_h[4u * QQ * DD];   // 64 MB fp16 mem
__device__ __align__(16) __half g_x_h[4 * BB * DD];    // fp16 X
__device__ float g_norm[4 * BB];
__device__ float g_scale[NCOMBO * BB];                 // 1/(ni*nj*T)

// ----------------------------------------------------------------------------
// PTX helpers (sm_103-safe: mma.sync / ldmatrix / cp.async only)
// ----------------------------------------------------------------------------
__device__ __forceinline__ uint32_t smem_to_u32(const void* p) {
    uint32_t a;
    asm("{ .reg .u64 t; cvta.to.shared.u64 t, %1; cvt.u32.u64 %0, t; }" : "=r"(a) : "l"(p));
    return a;
}

__device__ __forceinline__ void cp_async16(uint32_t saddr, const void* gaddr) {
    asm volatile("cp.async.cg.shared.global [%0], [%1], 16;" :: "r"(saddr), "l"(gaddr));
}
__device__ __forceinline__ void cp_commit() {
    asm volatile("cp.async.commit_group;" ::: "memory");
}
template <int N>
__device__ __forceinline__ void cp_wait() {
    asm volatile("cp.async.wait_group %0;" :: "n"(N) : "memory");
}

__device__ __forceinline__ void ldsm_x4(uint32_t* r, uint32_t addr) {
    asm volatile("ldmatrix.sync.aligned.m8n8.x4.shared.b16 {%0,%1,%2,%3}, [%4];"
                 : "=r"(r[0]), "=r"(r[1]), "=r"(r[2]), "=r"(r[3]) : "r"(addr));
}

__device__ __forceinline__ void mma_f16(float* d, const uint32_t* a, const uint32_t* b) {
    asm volatile(
        "mma.sync.aligned.m16n8k16.row.col.f32.f16.f16.f32 "
        "{%0,%1,%2,%3}, {%4,%5,%6,%7}, {%8,%9}, {%0,%1,%2,%3};"
        : "+f"(d[0]), "+f"(d[1]), "+f"(d[2]), "+f"(d[3])
        : "r"(a[0]), "r"(a[1]), "r"(a[2]), "r"(a[3]), "r"(b[0]), "r"(b[1]));
}

// ----------------------------------------------------------------------------
// Small helpers
// ----------------------------------------------------------------------------
__device__ __forceinline__ const float* sel4(int v, const float* a, const float* b,
                                             const float* c, const float* d) {
    return v == 0 ? a : (v == 1 ? b : (v == 2 ? c : d));
}

// ----------------------------------------------------------------------------
// k_norm: per-row L2 norms of the 4 X views (one warp per row)
// ----------------------------------------------------------------------------
__global__ void k_norm(const float* __restrict__ x0, const float* __restrict__ x1,
                       const float* __restrict__ x2, const float* __restrict__ x3) {
    int gw = (blockIdx.x * blockDim.x + threadIdx.x) >> 5;
    int lane = threadIdx.x & 31;
    if (gw >= 4 * BB) return;
    int v = gw >> 9, b = gw & (BB - 1);
    const float* row = sel4(v, x0, x1, x2, x3) + (size_t)b * DD;
    float s = 0.f;
#pragma unroll
    for (int k = 0; k < 8; k++) { float t = row[lane + k * 32]; s += t * t; }
#pragma unroll
    for (int o = 16; o; o >>= 1) s += __shfl_xor_sync(0xffffffffu, s, o);
    if (lane == 0) g_norm[gw] = sqrtf(s);
}

// ----------------------------------------------------------------------------
// k_prep_x: X -> fp16 scratch; Y -> tail of new_mem output
// grid (160, 4): bx<32 convert X (each thread 4 float4 = 16 floats), else Y copy
// ----------------------------------------------------------------------------
__global__ void k_prep_x(const float* __restrict__ x0, const float* __restrict__ x1,
                         const float* __restrict__ x2, const float* __restrict__ x3,
                         const float* __restrict__ y0, const float* __restrict__ y1,
                         const float* __restrict__ y2, const float* __restrict__ y3,
                         float* __restrict__ out_mem) {
    int v = blockIdx.y;
    int bx = blockIdx.x;
    int t = threadIdx.x;
    if (bx < 32) {
        int idx = bx * 1024 + t * 4;           // float4 index; 32768 per view
        const float4* src = reinterpret_cast<const float4*>(sel4(v, x0, x1, x2, x3));
        uint4 pk[2];
#pragma unroll
        for (int g = 0; g < 2; g++) {
            float4 f0 = src[idx + g * 2 + 0];
            float4 f1 = src[idx + g * 2 + 1];
            __half2 h0 = __floats2half2_rn(f0.x, f0.y);
            __half2 h1 = __floats2half2_rn(f0.z, f0.w);
            __half2 h2 = __floats2half2_rn(f1.x, f1.y);
            __half2 h3 = __floats2half2_rn(f1.z, f1.w);
            pk[g].x = *reinterpret_cast<uint32_t*>(&h0);
            pk[g].y = *reinterpret_cast<uint32_t*>(&h1);
            pk[g].z = *reinterpret_cast<uint32_t*>(&h2);
            pk[g].w = *reinterpret_cast<uint32_t*>(&h3);
        }
        uint4* dst = reinterpret_cast<uint4*>(g_x_h + (size_t)v * BB * DD);
        dst[idx / 2 + 0] = pk[0];
        dst[idx / 2 + 1] = pk[1];
    } else {
        int idx = (bx - 32) * 256 + t;         // < 32768 float4 per view
        float4 f = reinterpret_cast<const float4*>(sel4(v, y0, y1, y2, y3))[idx];
        reinterpret_cast<float4*>(out_mem)[(size_t)v * (QQ * DD / 4) + (size_t)(QQ - BB) * (DD / 4) + idx] = f;
    }
}

// ----------------------------------------------------------------------------
// k_self: self-dots (column 0, full fp32) + per-row scales.
// ----------------------------------------------------------------------------
__global__ void k_self(const float* __restrict__ x0, const float* __restrict__ x1,
                       const float* __restrict__ x2, const float* __restrict__ x3,
                       float* __restrict__ out) {
    int gw = (blockIdx.x * blockDim.x + threadIdx.x) >> 5;
    int lane = threadIdx.x & 31;
    if (gw >= NCOMBO * BB) return;
    int c = gw >> 9, b = gw & (BB - 1);
    int i = d_CI[c], j = d_CJ[c];
    const float* xi = sel4(i, x0, x1, x2, x3) + (size_t)b * DD;
    const float* xj = sel4(j, x0, x1, x2, x3) + (size_t)b * DD;
    float s = 0.f;
#pragma unroll
    for (int k = 0; k < 8; k++) s += xi[lane + k * 32] * xj[lane + k * 32];
#pragma unroll
    for (int o = 16; o; o >>= 1) s += __shfl_xor_sync(0xffffffffu, s, o);
    if (lane == 0) {
        float sc = 1.0f / (g_norm[i * BB + b] * g_norm[j * BB + b] * 0.07f);
        g_scale[c * BB + b] = sc;
        out[(size_t)c * BB * ROWL + (size_t)b * ROWL] = __expf(s * sc);
    }
}

// ----------------------------------------------------------------------------
// k_prep_mem: Mem -> fp16 scratch AND FIFO-shifted new_mem output.
// Each thread: 16 floats (4 float4). grid (2048, 4), 256 threads.
// ----------------------------------------------------------------------------
__global__ void k_prep_mem(const float* __restrict__ m0, const float* __restrict__ m1,
                           const float* __restrict__ m2, const float* __restrict__ m3,
                           float* __restrict__ out_mem) {
    int v = blockIdx.y;
    int idx = (blockIdx.x * 256 + threadIdx.x) * 4;   // float4 index, 4 per thread
    const float4* src = reinterpret_cast<const float4*>(sel4(v, m0, m1, m2, m3));
    float4 f[4];
#pragma unroll
    for (int g = 0; g < 4; g++) f[g] = src[idx + g];

    uint4 pk[2];
#pragma unroll
    for (int g = 0; g < 2; g++) {
        __half2 h0 = __floats2half2_rn(f[2 * g].x, f[2 * g].y);
        __half2 h1 = __floats2half2_rn(f[2 * g].z, f[2 * g].w);
        __half2 h2 = __floats2half2_rn(f[2 * g + 1].x, f[2 * g + 1].y);
        __half2 h3 = __floats2half2_rn(f[2 * g + 1].z, f[2 * g + 1].w);
        pk[g].x = *reinterpret_cast<uint32_t*>(&h0);
        pk[g].y = *reinterpret_cast<uint32_t*>(&h1);
        pk[g].z = *reinterpret_cast<uint32_t*>(&h2);
        pk[g].w = *reinterpret_cast<uint32_t*>(&h3);
    }
    uint4* dsth = reinterpret_cast<uint4*>(g_m_h + (size_t)v * QQ * DD);
    dsth[idx / 2 + 0] = pk[0];
    dsth[idx / 2 + 1] = pk[1];

    // FIFO shift: float4 slots [B*D/4, Q*D/4) -> [0, (Q-B)*D/4)
    const int shift = BB * (DD / 4);
    float4* dst = reinterpret_cast<float4*>(out_mem) + (size_t)v * (QQ * DD / 4) - shift;
    if (idx >= shift) {
#pragma unroll
        for (int g = 0; g < 4; g++) dst[idx + g] = f[g];
    }
}

// ----------------------------------------------------------------------------
// k_gemm: single-pass fp16 mma.sync GEMM + exp epilogue.
// Block tile M=128 x N=128, K=256 in 4 chunks of 64, cp.async double-buffered.
// 8 warps: 2 (m) x 4 (n); warp tile 64x32. 2 CTAs/SM.
// Smem: 2 tiles (A,B) x 128 rows x 128B, padded stride 144B, double buffered.
// ----------------------------------------------------------------------------
#define TS_ROWB   144
#define TILE_B    (128 * TS_ROWB)          // 18432
#define BUF_B     (2 * TILE_B)             // 36864 (A, B)
#define GEMM_SMEM (2 * BUF_B)              // 73728

__global__ void __launch_bounds__(256, 2) k_gemm(float* __restrict__ out) {
    extern __shared__ char smem[];
    const uint32_t sb = smem_to_u32(smem);
    const int tid = threadIdx.x, lane = tid & 31, wid = tid >> 5;
    const int wm = wid & 1, wn = wid >> 1;
    const int cm = blockIdx.x;
    const int c = cm >> 2, mtile = cm & 3, ntile = blockIdx.y;
    const int i = d_CI[c], j = d_CJ[c];

    const __half* srcA = g_x_h + ((size_t)i * BB + mtile * 128) * DD;
    const __half* srcB = g_m_h + ((size_t)j * QQ + (size_t)ntile * 128) * DD;

    // per-thread load slots: 4 uint4 per tile, row = idx/8, seg = idx%8
    const int l_row[4] = { (tid + 0 * 256) >> 3, (tid + 1 * 256) >> 3,
                           (tid + 2 * 256) >> 3, (tid + 3 * 256) >> 3 };
    const int l_seg = tid & 7;

    auto issue_chunk = [&](int kc, int buf) {
        uint32_t sbase = sb + buf * BUF_B;
#pragma unroll
        for (int r = 0; r < 4; r++) {
            const __half* gA = srcA + (size_t)l_row[r] * DD + kc * 64 + l_seg * 8;
            const __half* gB = srcB + (size_t)l_row[r] * DD + kc * 64 + l_seg * 8;
            uint32_t soff = l_row[r] * TS_ROWB + l_seg * 16;
            cp_async16(sbase + soff, gA);
            cp_async16(sbase + TILE_B + soff, gB);
        }
        cp_commit();
    };

    float acc[4][4][4];
#pragma unroll
    for (int a = 0; a < 4; a++)
#pragma unroll
        for (int b = 0; b < 4; b++)
#pragma unroll
            for (int k = 0; k < 4; k++) acc[a][b][k] = 0.f;

    // ldmatrix base offsets (within a buffer)
    const uint32_t a_lane_off = (uint32_t)((lane & 15) * TS_ROWB + (lane >> 4) * 16);
    const uint32_t b_lane_off = (uint32_t)(((lane & 7) + ((lane >> 4) << 3)) * TS_ROWB
                                           + (((lane >> 3) & 1) * 16));

    issue_chunk(0, 0);

#pragma unroll 1
    for (int kc = 0; kc < 4; kc++) {
        if (kc < 3) issue_chunk(kc + 1, (kc + 1) & 1);
        if (kc < 3) cp_wait<1>(); else cp_wait<0>();
        __syncthreads();

        const uint32_t bufb = sb + (kc & 1) * BUF_B;
        const uint32_t aT = bufb + (wm * 64) * TS_ROWB + a_lane_off;
        const uint32_t bT = bufb + TILE_B + (wn * 32) * TS_ROWB + b_lane_off;

#pragma unroll
        for (int step = 0; step < 4; step++) {
            const uint32_t koff = step * 32;   // 16 fp16 = 32 bytes
            uint32_t bh[8];
            ldsm_x4(bh + 0, bT + koff);                       // n 0-15
            ldsm_x4(bh + 4, bT + 16 * TS_ROWB + koff);        // n 16-31
#pragma unroll
            for (int mi = 0; mi < 4; mi++) {
                uint32_t ah[4];
                ldsm_x4(ah, aT + mi * 16 * TS_ROWB + koff);
#pragma unroll
                for (int ni = 0; ni < 4; ni++)
                    mma_f16(acc[mi][ni], ah, bh + ni * 2);
            }
        }
        __syncthreads();
    }

    // Epilogue: exp(d * scale_row) -> out
    const int r0 = lane >> 2;
    const int cpair = (lane & 3) * 2;
#pragma unroll
    for (int mi = 0; mi < 4; mi++) {
        const int grow0 = mtile * 128 + wm * 64 + mi * 16 + r0;
        const float scl0 = g_scale[c * BB + grow0];
        const float scl1 = g_scale[c * BB + grow0 + 8];
        const size_t base0 = ((size_t)c * BB + grow0) * ROWL;
        const size_t base1 = base0 + (size_t)8 * ROWL;
#pragma unroll
        for (int ni = 0; ni < 4; ni++) {
            const size_t col = 1 + (size_t)ntile * 128 + wn * 32 + ni * 8 + cpair;
            out[base0 + col + 0] = __expf(acc[mi][ni][0] * scl0);
            out[base0 + col + 1] = __expf(acc[mi][ni][1] * scl0);
            out[base1 + col + 0] = __expf(acc[mi][ni][2] * scl1);
            out[base1 + col + 1] = __expf(acc[mi][ni][3] * scl1);
        }
    }
}

// ----------------------------------------------------------------------------
// kernel_launch — input order detected from in_sizes (interleaved vs grouped)
// ----------------------------------------------------------------------------
extern "C" void kernel_launch(void* const* d_in, const int* in_sizes, int n_in,
                              void* d_out, int out_size) {
    (void)n_in; (void)out_size;
    const float* x[4]; const float* y[4]; const float* m[4];
    const bool interleaved = (in_sizes[2] == QQ * DD);
    for (int v = 0; v < 4; v++) {
        if (interleaved) {
            x[v] = (const float*)d_in[3 * v + 0];
            y[v] = (const float*)d_in[3 * v + 1];
            m[v] = (const float*)d_in[3 * v + 2];
        } else {
            x[v] = (const float*)d_in[v];
            y[v] = (const float*)d_in[4 + v];
            m[v] = (const float*)d_in[8 + v];
        }
    }
    float* out = (float*)d_out;
    float* out_mem = out + (size_t)NCOMBO * BB * ROWL;

    cudaFuncSetAttribute(k_gemm, cudaFuncAttributeMaxDynamicSharedMemorySize, GEMM_SMEM);

    k_norm<<<256, 256>>>(x[0], x[1], x[2], x[3]);
    k_prep_x<<<dim3(160, 4), 256>>>(x[0], x[1], x[2], x[3],
                                    y[0], y[1], y[2], y[3], out_mem);
    k_self<<<512, 256>>>(x[0], x[1], x[2], x[3], out);
    k_prep_mem<<<dim3(2048, 4), 256>>>(m[0], m[1], m[2], m[3], out_mem);
    k_gemm<<<dim3(32, 256), 256, GEMM_SMEM>>>(out);
}

// round 7
// speedup vs baseline: 3.8010x; 1.0167x over previous
#include <cuda_runtime.h>
#include <cuda_fp16.h>
#include <cstdint>
#include <cstddef>

// ----------------------------------------------------------------------------
// Problem constants
// ----------------------------------------------------------------------------
#define BB   512
#define QQ   32768
#define DD   256
#define ROWL 32769            // 1 + Q
#define NCOMBO 8

__constant__ int d_CI[8] = {0, 0, 0, 1, 1, 2, 2, 3};
__constant__ int d_CJ[8] = {1, 2, 3, 0, 2, 0, 1, 0};

// ----------------------------------------------------------------------------
// Scratch (device globals; no allocation allowed)
// ----------------------------------------------------------------------------
__device__ __align__(16) __half g_m_h[4u * QQ * DD];   // 64 MB fp16 mem
__device__ __align__(16) __half g_x_h[4 * BB * DD];    // fp16 X
__device__ float g_scale[NCOMBO * BB];                 // 1/(ni*nj*T)

// ----------------------------------------------------------------------------
// PTX helpers (sm_103-safe: mma.sync / ldmatrix / cp.async only)
// ----------------------------------------------------------------------------
__device__ __forceinline__ uint32_t smem_to_u32(const void* p) {
    uint32_t a;
    asm("{ .reg .u64 t; cvta.to.shared.u64 t, %1; cvt.u32.u64 %0, t; }" : "=r"(a) : "l"(p));
    return a;
}

__device__ __forceinline__ void cp_async16(uint32_t saddr, const void* gaddr) {
    asm volatile("cp.async.cg.shared.global [%0], [%1], 16;" :: "r"(saddr), "l"(gaddr));
}
__device__ __forceinline__ void cp_commit() {
    asm volatile("cp.async.commit_group;" ::: "memory");
}
template <int N>
__device__ __forceinline__ void cp_wait() {
    asm volatile("cp.async.wait_group %0;" :: "n"(N) : "memory");
}

__device__ __forceinline__ void ldsm_x4(uint32_t* r, uint32_t addr) {
    asm volatile("ldmatrix.sync.aligned.m8n8.x4.shared.b16 {%0,%1,%2,%3}, [%4];"
                 : "=r"(r[0]), "=r"(r[1]), "=r"(r[2]), "=r"(r[3]) : "r"(addr));
}

__device__ __forceinline__ void mma_f16(float* d, const uint32_t* a, const uint32_t* b) {
    asm volatile(
        "mma.sync.aligned.m16n8k16.row.col.f32.f16.f16.f32 "
        "{%0,%1,%2,%3}, {%4,%5,%6,%7}, {%8,%9}, {%0,%1,%2,%3};"
        : "+f"(d[0]), "+f"(d[1]), "+f"(d[2]), "+f"(d[3])
        : "r"(a[0]), "r"(a[1]), "r"(a[2]), "r"(a[3]), "r"(b[0]), "r"(b[1]));
}

// ----------------------------------------------------------------------------
// Small helpers
// ----------------------------------------------------------------------------
__device__ __forceinline__ const float* sel4(int v, const float* a, const float* b,
                                             const float* c, const float* d) {
    return v == 0 ? a : (v == 1 ? b : (v == 2 ? c : d));
}

// ----------------------------------------------------------------------------
// k_prep_x: X -> fp16 scratch; Y -> tail of new_mem output
// grid (160, 4): bx<32 convert X (each thread 4 float4 = 16 floats), else Y copy
// ----------------------------------------------------------------------------
__global__ void k_prep_x(const float* __restrict__ x0, const float* __restrict__ x1,
                         const float* __restrict__ x2, const float* __restrict__ x3,
                         const float* __restrict__ y0, const float* __restrict__ y1,
                         const float* __restrict__ y2, const float* __restrict__ y3,
                         float* __restrict__ out_mem) {
    int v = blockIdx.y;
    int bx = blockIdx.x;
    int t = threadIdx.x;
    if (bx < 32) {
        int idx = bx * 1024 + t * 4;           // float4 index; 32768 per view
        const float4* src = reinterpret_cast<const float4*>(sel4(v, x0, x1, x2, x3));
        uint4 pk[2];
#pragma unroll
        for (int g = 0; g < 2; g++) {
            float4 f0 = src[idx + g * 2 + 0];
            float4 f1 = src[idx + g * 2 + 1];
            __half2 h0 = __floats2half2_rn(f0.x, f0.y);
            __half2 h1 = __floats2half2_rn(f0.z, f0.w);
            __half2 h2 = __floats2half2_rn(f1.x, f1.y);
            __half2 h3 = __floats2half2_rn(f1.z, f1.w);
            pk[g].x = *reinterpret_cast<uint32_t*>(&h0);
            pk[g].y = *reinterpret_cast<uint32_t*>(&h1);
            pk[g].z = *reinterpret_cast<uint32_t*>(&h2);
            pk[g].w = *reinterpret_cast<uint32_t*>(&h3);
        }
        uint4* dst = reinterpret_cast<uint4*>(g_x_h + (size_t)v * BB * DD);
        dst[idx / 2 + 0] = pk[0];
        dst[idx / 2 + 1] = pk[1];
    } else {
        int idx = (bx - 32) * 256 + t;         // < 32768 float4 per view
        float4 f = reinterpret_cast<const float4*>(sel4(v, y0, y1, y2, y3))[idx];
        reinterpret_cast<float4*>(out_mem)[(size_t)v * (QQ * DD / 4) + (size_t)(QQ - BB) * (DD / 4) + idx] = f;
    }
}

// ----------------------------------------------------------------------------
// k_self: self-dots (column 0, full fp32) + norms + per-row scales.
// One warp per (combo,row); norms computed inline (no k_norm kernel).
// ----------------------------------------------------------------------------
__global__ void k_self(const float* __restrict__ x0, const float* __restrict__ x1,
                       const float* __restrict__ x2, const float* __restrict__ x3,
                       float* __restrict__ out) {
    int gw = (blockIdx.x * blockDim.x + threadIdx.x) >> 5;
    int lane = threadIdx.x & 31;
    if (gw >= NCOMBO * BB) return;
    int c = gw >> 9, b = gw & (BB - 1);
    int i = d_CI[c], j = d_CJ[c];
    const float* xi = sel4(i, x0, x1, x2, x3) + (size_t)b * DD;
    const float* xj = sel4(j, x0, x1, x2, x3) + (size_t)b * DD;
    float s = 0.f, ni = 0.f, nj = 0.f;
#pragma unroll
    for (int k = 0; k < 8; k++) {
        float a = xi[lane + k * 32], d = xj[lane + k * 32];
        s = fmaf(a, d, s);
        ni = fmaf(a, a, ni);
        nj = fmaf(d, d, nj);
    }
#pragma unroll
    for (int o = 16; o; o >>= 1) {
        s  += __shfl_xor_sync(0xffffffffu, s, o);
        ni += __shfl_xor_sync(0xffffffffu, ni, o);
        nj += __shfl_xor_sync(0xffffffffu, nj, o);
    }
    if (lane == 0) {
        float sc = 1.0f / (sqrtf(ni) * sqrtf(nj) * 0.07f);
        g_scale[c * BB + b] = sc;
        out[(size_t)c * BB * ROWL + (size_t)b * ROWL] = __expf(s * sc);
    }
}

// ----------------------------------------------------------------------------
// k_prep_mem: Mem -> fp16 scratch ONLY (FIFO copy moved into k_gemm).
// Each thread: 8 floats (2 float4). grid (4096, 4), 256 threads.
// ----------------------------------------------------------------------------
__global__ void k_prep_mem(const float* __restrict__ m0, const float* __restrict__ m1,
                           const float* __restrict__ m2, const float* __restrict__ m3) {
    int v = blockIdx.y;
    int idx = (blockIdx.x * 256 + threadIdx.x) * 2;   // float4 index, 2 per thread
    const float4* src = reinterpret_cast<const float4*>(sel4(v, m0, m1, m2, m3));
    float4 f0 = src[idx + 0];
    float4 f1 = src[idx + 1];
    __half2 h0 = __floats2half2_rn(f0.x, f0.y);
    __half2 h1 = __floats2half2_rn(f0.z, f0.w);
    __half2 h2 = __floats2half2_rn(f1.x, f1.y);
    __half2 h3 = __floats2half2_rn(f1.z, f1.w);
    uint4 pk;
    pk.x = *reinterpret_cast<uint32_t*>(&h0);
    pk.y = *reinterpret_cast<uint32_t*>(&h1);
    pk.z = *reinterpret_cast<uint32_t*>(&h2);
    pk.w = *reinterpret_cast<uint32_t*>(&h3);
    reinterpret_cast<uint4*>(g_m_h + (size_t)v * QQ * DD)[idx / 2] = pk;
}

// ----------------------------------------------------------------------------
// k_gemm: single-pass fp16 mma.sync GEMM + exp epilogue + fused FIFO copy.
// Block tile M=128 x N=128, K=256 in 4 chunks of 64, cp.async double-buffered.
// 8 warps: 2 (m) x 4 (n); warp tile 64x32. 2 CTAs/SM.
// FIFO copy: each of the 8192 CTAs copies exactly 1008 float4 of the
// mem[B:, :] -> new_mem[:Q-B, :] shift (8192*1008 = 4*(Q-B)*D/4 exactly).
// ----------------------------------------------------------------------------
#define TS_ROWB   144
#define TILE_B    (128 * TS_ROWB)          // 18432
#define BUF_B     (2 * TILE_B)             // 36864 (A, B)
#define GEMM_SMEM (2 * BUF_B)              // 73728
#define CPY_PER_CTA 1008
#define CPY_PER_VIEW ((QQ - BB) * DD / 4)  // 2064384 float4

__global__ void __launch_bounds__(256, 2) k_gemm(float* __restrict__ out,
                                                 const float* __restrict__ m0,
                                                 const float* __restrict__ m1,
                                                 const float* __restrict__ m2,
                                                 const float* __restrict__ m3,
                                                 float* __restrict__ out_mem) {
    extern __shared__ char smem[];
    const uint32_t sb = smem_to_u32(smem);
    const int tid = threadIdx.x, lane = tid & 31, wid = tid >> 5;
    const int wm = wid & 1, wn = wid >> 1;
    const int cm = blockIdx.x;
    const int c = cm >> 2, mtile = cm & 3, ntile = blockIdx.y;
    const int i = d_CI[c], j = d_CJ[c];

    const __half* srcA = g_x_h + ((size_t)i * BB + mtile * 128) * DD;
    const __half* srcB = g_m_h + ((size_t)j * QQ + (size_t)ntile * 128) * DD;

    // per-thread load slots: 4 uint4 per tile, row = idx/8, seg = idx%8
    const int l_row[4] = { (tid + 0 * 256) >> 3, (tid + 1 * 256) >> 3,
                           (tid + 2 * 256) >> 3, (tid + 3 * 256) >> 3 };
    const int l_seg = tid & 7;

    auto issue_chunk = [&](int kc, int buf) {
        uint32_t sbase = sb + buf * BUF_B;
#pragma unroll
        for (int r = 0; r < 4; r++) {
            const __half* gA = srcA + (size_t)l_row[r] * DD + kc * 64 + l_seg * 8;
            const __half* gB = srcB + (size_t)l_row[r] * DD + kc * 64 + l_seg * 8;
            uint32_t soff = l_row[r] * TS_ROWB + l_seg * 16;
            cp_async16(sbase + soff, gA);
            cp_async16(sbase + TILE_B + soff, gB);
        }
        cp_commit();
    };

    issue_chunk(0, 0);

    // ---- fused FIFO shift copy (overlaps with first cp.async chunk) ----
    {
        const int gid = blockIdx.y * 32 + blockIdx.x;          // 0..8191
        int u0 = gid * CPY_PER_CTA + tid;
#pragma unroll
        for (int g = 0; g < 4; g++) {
            int u = u0 + g * 256;
            if (g < 3 || u < (gid + 1) * CPY_PER_CTA) {
                int v = u / CPY_PER_VIEW;
                int rem = u - v * CPY_PER_VIEW;
                const float4* s4 = reinterpret_cast<const float4*>(sel4(v, m0, m1, m2, m3));
                float4 f = s4[BB * (DD / 4) + rem];
                reinterpret_cast<float4*>(out_mem)[(size_t)v * (QQ * DD / 4) + rem] = f;
            }
        }
    }

    float acc[4][4][4];
#pragma unroll
    for (int a = 0; a < 4; a++)
#pragma unroll
        for (int b = 0; b < 4; b++)
#pragma unroll
            for (int k = 0; k < 4; k++) acc[a][b][k] = 0.f;

    // ldmatrix base offsets (within a buffer)
    const uint32_t a_lane_off = (uint32_t)((lane & 15) * TS_ROWB + (lane >> 4) * 16);
    const uint32_t b_lane_off = (uint32_t)(((lane & 7) + ((lane >> 4) << 3)) * TS_ROWB
                                           + (((lane >> 3) & 1) * 16));

#pragma unroll 1
    for (int kc = 0; kc < 4; kc++) {
        if (kc < 3) issue_chunk(kc + 1, (kc + 1) & 1);
        if (kc < 3) cp_wait<1>(); else cp_wait<0>();
        __syncthreads();

        const uint32_t bufb = sb + (kc & 1) * BUF_B;
        const uint32_t aT = bufb + (wm * 64) * TS_ROWB + a_lane_off;
        const uint32_t bT = bufb + TILE_B + (wn * 32) * TS_ROWB + b_lane_off;

#pragma unroll
        for (int step = 0; step < 4; step++) {
            const uint32_t koff = step * 32;   // 16 fp16 = 32 bytes
            uint32_t bh[8];
            ldsm_x4(bh + 0, bT + koff);                       // n 0-15
            ldsm_x4(bh + 4, bT + 16 * TS_ROWB + koff);        // n 16-31
#pragma unroll
            for (int mi = 0; mi < 4; mi++) {
                uint32_t ah[4];
                ldsm_x4(ah, aT + mi * 16 * TS_ROWB + koff);
#pragma unroll
                for (int ni = 0; ni < 4; ni++)
                    mma_f16(acc[mi][ni], ah, bh + ni * 2);
            }
        }
        __syncthreads();
    }

    // Epilogue: exp(d * scale_row) -> out
    const int r0 = lane >> 2;
    const int cpair = (lane & 3) * 2;
#pragma unroll
    for (int mi = 0; mi < 4; mi++) {
        const int grow0 = mtile * 128 + wm * 64 + mi * 16 + r0;
        const float scl0 = g_scale[c * BB + grow0];
        const float scl1 = g_scale[c * BB + grow0 + 8];
        const size_t base0 = ((size_t)c * BB + grow0) * ROWL;
        const size_t base1 = base0 + (size_t)8 * ROWL;
#pragma unroll
        for (int ni = 0; ni < 4; ni++) {
            const size_t col = 1 + (size_t)ntile * 128 + wn * 32 + ni * 8 + cpair;
            out[base0 + col + 0] = __expf(acc[mi][ni][0] * scl0);
            out[base0 + col + 1] = __expf(acc[mi][ni][1] * scl0);
            out[base1 + col + 0] = __expf(acc[mi][ni][2] * scl1);
            out[base1 + col + 1] = __expf(acc[mi][ni][3] * scl1);
        }
    }
}

// ----------------------------------------------------------------------------
// kernel_launch — input order detected from in_sizes (interleaved vs grouped)
// ----------------------------------------------------------------------------
extern "C" void kernel_launch(void* const* d_in, const int* in_sizes, int n_in,
                              void* d_out, int out_size) {
    (void)n_in; (void)out_size;
    const float* x[4]; const float* y[4]; const float* m[4];
    const bool interleaved = (in_sizes[2] == QQ * DD);
    for (int v = 0; v < 4; v++) {
        if (interleaved) {
            x[v] = (const float*)d_in[3 * v + 0];
            y[v] = (const float*)d_in[3 * v + 1];
            m[v] = (const float*)d_in[3 * v + 2];
        } else {
            x[v] = (const float*)d_in[v];
            y[v] = (const float*)d_in[4 + v];
            m[v] = (const float*)d_in[8 + v];
        }
    }
    float* out = (float*)d_out;
    float* out_mem = out + (size_t)NCOMBO * BB * ROWL;

    cudaFuncSetAttribute(k_gemm, cudaFuncAttributeMaxDynamicSharedMemorySize, GEMM_SMEM);

    k_prep_x<<<dim3(160, 4), 256>>>(x[0], x[1], x[2], x[3],
                                    y[0], y[1], y[2], y[3], out_mem);
    k_self<<<512, 256>>>(x[0], x[1], x[2], x[3], out);
    k_prep_mem<<<dim3(4096, 4), 256>>>(m[0], m[1], m[2], m[3]);
    k_gemm<<<dim3(32, 256), 256, GEMM_SMEM>>>(out, m[0], m[1], m[2], m[3], out_mem);
}

// round 8
// speedup vs baseline: 4.8371x; 1.2726x over previous
#include <cuda_runtime.h>
#include <cuda_fp16.h>
#include <cstdint>
#include <cstddef>

// ----------------------------------------------------------------------------
// Problem constants
// ----------------------------------------------------------------------------
#define BB   512
#define QQ   32768
#define DD   256
#define ROWL 32769            // 1 + Q
#define NCOMBO 8

__constant__ int d_CI[8] = {0, 0, 0, 1, 1, 2, 2, 3};
__constant__ int d_CJ[8] = {1, 2, 3, 0, 2, 0, 1, 0};

// ----------------------------------------------------------------------------
// Scratch (device globals; no allocation allowed)
// ----------------------------------------------------------------------------
__device__ __align__(16) __half g_m_h[4u * QQ * DD];   // 64 MB fp16 mem
__device__ __align__(16) __half g_x_h[4 * BB * DD];    // fp16 X
__device__ float g_scale[NCOMBO * BB];                 // 1/(ni*nj*T)

// ----------------------------------------------------------------------------
// PTX helpers (sm_103-safe: mma.sync / ldmatrix / cp.async only)
// ----------------------------------------------------------------------------
__device__ __forceinline__ uint32_t smem_to_u32(const void* p) {
    uint32_t a;
    asm("{ .reg .u64 t; cvta.to.shared.u64 t, %1; cvt.u32.u64 %0, t; }" : "=r"(a) : "l"(p));
    return a;
}

__device__ __forceinline__ void cp_async16(uint32_t saddr, const void* gaddr) {
    asm volatile("cp.async.cg.shared.global [%0], [%1], 16;" :: "r"(saddr), "l"(gaddr));
}
__device__ __forceinline__ void cp_commit() {
    asm volatile("cp.async.commit_group;" ::: "memory");
}
template <int N>
__device__ __forceinline__ void cp_wait() {
    asm volatile("cp.async.wait_group %0;" :: "n"(N) : "memory");
}

__device__ __forceinline__ void ldsm_x4(uint32_t* r, uint32_t addr) {
    asm volatile("ldmatrix.sync.aligned.m8n8.x4.shared.b16 {%0,%1,%2,%3}, [%4];"
                 : "=r"(r[0]), "=r"(r[1]), "=r"(r[2]), "=r"(r[3]) : "r"(addr));
}

__device__ __forceinline__ void mma_f16(float* d, const uint32_t* a, const uint32_t* b) {
    asm volatile(
        "mma.sync.aligned.m16n8k16.row.col.f32.f16.f16.f32 "
        "{%0,%1,%2,%3}, {%4,%5,%6,%7}, {%8,%9}, {%0,%1,%2,%3};"
        : "+f"(d[0]), "+f"(d[1]), "+f"(d[2]), "+f"(d[3])
        : "r"(a[0]), "r"(a[1]), "r"(a[2]), "r"(a[3]), "r"(b[0]), "r"(b[1]));
}

// ----------------------------------------------------------------------------
// Small helpers
// ----------------------------------------------------------------------------
__device__ __forceinline__ const float* sel4(int v, const float* a, const float* b,
                                             const float* c, const float* d) {
    return v == 0 ? a : (v == 1 ? b : (v == 2 ? c : d));
}

// ----------------------------------------------------------------------------
// k_prep_x: X -> fp16 scratch; Y -> tail of new_mem output
// grid (160, 4): bx<32 convert X (each thread 4 float4 = 16 floats), else Y copy
// ----------------------------------------------------------------------------
__global__ void k_prep_x(const float* __restrict__ x0, const float* __restrict__ x1,
                         const float* __restrict__ x2, const float* __restrict__ x3,
                         const float* __restrict__ y0, const float* __restrict__ y1,
                         const float* __restrict__ y2, const float* __restrict__ y3,
                         float* __restrict__ out_mem) {
    int v = blockIdx.y;
    int bx = blockIdx.x;
    int t = threadIdx.x;
    if (bx < 32) {
        int idx = bx * 1024 + t * 4;           // float4 index; 32768 per view
        const float4* src = reinterpret_cast<const float4*>(sel4(v, x0, x1, x2, x3));
        uint4 pk[2];
#pragma unroll
        for (int g = 0; g < 2; g++) {
            float4 f0 = src[idx + g * 2 + 0];
            float4 f1 = src[idx + g * 2 + 1];
            __half2 h0 = __floats2half2_rn(f0.x, f0.y);
            __half2 h1 = __floats2half2_rn(f0.z, f0.w);
            __half2 h2 = __floats2half2_rn(f1.x, f1.y);
            __half2 h3 = __floats2half2_rn(f1.z, f1.w);
            pk[g].x = *reinterpret_cast<uint32_t*>(&h0);
            pk[g].y = *reinterpret_cast<uint32_t*>(&h1);
            pk[g].z = *reinterpret_cast<uint32_t*>(&h2);
            pk[g].w = *reinterpret_cast<uint32_t*>(&h3);
        }
        uint4* dst = reinterpret_cast<uint4*>(g_x_h + (size_t)v * BB * DD);
        dst[idx / 2 + 0] = pk[0];
        dst[idx / 2 + 1] = pk[1];
    } else {
        int idx = (bx - 32) * 256 + t;         // < 32768 float4 per view
        float4 f = reinterpret_cast<const float4*>(sel4(v, y0, y1, y2, y3))[idx];
        reinterpret_cast<float4*>(out_mem)[(size_t)v * (QQ * DD / 4) + (size_t)(QQ - BB) * (DD / 4) + idx] = f;
    }
}

// ----------------------------------------------------------------------------
// k_self: self-dots (column 0, full fp32) + norms + per-row scales.
// ----------------------------------------------------------------------------
__global__ void k_self(const float* __restrict__ x0, const float* __restrict__ x1,
                       const float* __restrict__ x2, const float* __restrict__ x3,
                       float* __restrict__ out) {
    int gw = (blockIdx.x * blockDim.x + threadIdx.x) >> 5;
    int lane = threadIdx.x & 31;
    if (gw >= NCOMBO * BB) return;
    int c = gw >> 9, b = gw & (BB - 1);
    int i = d_CI[c], j = d_CJ[c];
    const float* xi = sel4(i, x0, x1, x2, x3) + (size_t)b * DD;
    const float* xj = sel4(j, x0, x1, x2, x3) + (size_t)b * DD;
    float s = 0.f, ni = 0.f, nj = 0.f;
#pragma unroll
    for (int k = 0; k < 8; k++) {
        float a = xi[lane + k * 32], d = xj[lane + k * 32];
        s = fmaf(a, d, s);
        ni = fmaf(a, a, ni);
        nj = fmaf(d, d, nj);
    }
#pragma unroll
    for (int o = 16; o; o >>= 1) {
        s  += __shfl_xor_sync(0xffffffffu, s, o);
        ni += __shfl_xor_sync(0xffffffffu, ni, o);
        nj += __shfl_xor_sync(0xffffffffu, nj, o);
    }
    if (lane == 0) {
        float sc = 1.0f / (sqrtf(ni) * sqrtf(nj) * 0.07f);
        g_scale[c * BB + b] = sc;
        out[(size_t)c * BB * ROWL + (size_t)b * ROWL] = __expf(s * sc);
    }
}

// ----------------------------------------------------------------------------
// k_prep_mem: Mem -> fp16 scratch ONLY (FIFO copy fused into k_gemm).
// ----------------------------------------------------------------------------
__global__ void k_prep_mem(const float* __restrict__ m0, const float* __restrict__ m1,
                           const float* __restrict__ m2, const float* __restrict__ m3) {
    int v = blockIdx.y;
    int idx = (blockIdx.x * 256 + threadIdx.x) * 2;   // float4 index, 2 per thread
    const float4* src = reinterpret_cast<const float4*>(sel4(v, m0, m1, m2, m3));
    float4 f0 = src[idx + 0];
    float4 f1 = src[idx + 1];
    __half2 h0 = __floats2half2_rn(f0.x, f0.y);
    __half2 h1 = __floats2half2_rn(f0.z, f0.w);
    __half2 h2 = __floats2half2_rn(f1.x, f1.y);
    __half2 h3 = __floats2half2_rn(f1.z, f1.w);
    uint4 pk;
    pk.x = *reinterpret_cast<uint32_t*>(&h0);
    pk.y = *reinterpret_cast<uint32_t*>(&h1);
    pk.z = *reinterpret_cast<uint32_t*>(&h2);
    pk.w = *reinterpret_cast<uint32_t*>(&h3);
    reinterpret_cast<uint4*>(g_m_h + (size_t)v * QQ * DD)[idx / 2] = pk;
}

// ----------------------------------------------------------------------------
// k_gemm: single-pass fp16 mma.sync GEMM + smem-transposed exp epilogue
//         + fused FIFO copy.
// Block tile M=128 x N=128, K=256 in 4 chunks of 64, cp.async double-buffered.
// 8 warps: 2 (m) x 4 (n); warp tile 64x32. 2 CTAs/SM.
// Epilogue: exp in regs -> STS to padded 128x132 fp32 tile -> coalesced STG.
// ----------------------------------------------------------------------------
#define TS_ROWB   144
#define TILE_B    (128 * TS_ROWB)          // 18432
#define BUF_B     (2 * TILE_B)             // 36864 (A, B)
#define GEMM_SMEM (2 * BUF_B)              // 73728 (>= 128*132*4 = 67584)
#define EPI_STRIDE 132
#define CPY_PER_CTA 1008
#define CPY_PER_VIEW ((QQ - BB) * DD / 4)  // 2064384 float4

__global__ void __launch_bounds__(256, 2) k_gemm(float* __restrict__ out,
                                                 const float* __restrict__ m0,
                                                 const float* __restrict__ m1,
                                                 const float* __restrict__ m2,
                                                 const float* __restrict__ m3,
                                                 float* __restrict__ out_mem) {
    extern __shared__ char smem[];
    const uint32_t sb = smem_to_u32(smem);
    const int tid = threadIdx.x, lane = tid & 31, wid = tid >> 5;
    const int wm = wid & 1, wn = wid >> 1;
    const int cm = blockIdx.x;
    const int c = cm >> 2, mtile = cm & 3, ntile = blockIdx.y;
    const int i = d_CI[c], j = d_CJ[c];

    const __half* srcA = g_x_h + ((size_t)i * BB + mtile * 128) * DD;
    const __half* srcB = g_m_h + ((size_t)j * QQ + (size_t)ntile * 128) * DD;

    // per-thread load slots: 4 uint4 per tile, row = idx/8, seg = idx%8
    const int l_row[4] = { (tid + 0 * 256) >> 3, (tid + 1 * 256) >> 3,
                           (tid + 2 * 256) >> 3, (tid + 3 * 256) >> 3 };
    const int l_seg = tid & 7;

    auto issue_chunk = [&](int kc, int buf) {
        uint32_t sbase = sb + buf * BUF_B;
#pragma unroll
        for (int r = 0; r < 4; r++) {
            const __half* gA = srcA + (size_t)l_row[r] * DD + kc * 64 + l_seg * 8;
            const __half* gB = srcB + (size_t)l_row[r] * DD + kc * 64 + l_seg * 8;
            uint32_t soff = l_row[r] * TS_ROWB + l_seg * 16;
            cp_async16(sbase + soff, gA);
            cp_async16(sbase + TILE_B + soff, gB);
        }
        cp_commit();
    };

    issue_chunk(0, 0);

    // ---- fused FIFO shift copy (overlaps with first cp.async chunk) ----
    {
        const int gid = blockIdx.y * 32 + blockIdx.x;          // 0..8191
        int u0 = gid * CPY_PER_CTA + tid;
#pragma unroll
        for (int g = 0; g < 4; g++) {
            int u = u0 + g * 256;
            if (g < 3 || u < (gid + 1) * CPY_PER_CTA) {
                int v = u / CPY_PER_VIEW;
                int rem = u - v * CPY_PER_VIEW;
                const float4* s4 = reinterpret_cast<const float4*>(sel4(v, m0, m1, m2, m3));
                float4 f = s4[BB * (DD / 4) + rem];
                reinterpret_cast<float4*>(out_mem)[(size_t)v * (QQ * DD / 4) + rem] = f;
            }
        }
    }

    float acc[4][4][4];
#pragma unroll
    for (int a = 0; a < 4; a++)
#pragma unroll
        for (int b = 0; b < 4; b++)
#pragma unroll
            for (int k = 0; k < 4; k++) acc[a][b][k] = 0.f;

    // ldmatrix base offsets (within a buffer)
    const uint32_t a_lane_off = (uint32_t)((lane & 15) * TS_ROWB + (lane >> 4) * 16);
    const uint32_t b_lane_off = (uint32_t)(((lane & 7) + ((lane >> 4) << 3)) * TS_ROWB
                                           + (((lane >> 3) & 1) * 16));

#pragma unroll 1
    for (int kc = 0; kc < 4; kc++) {
        if (kc < 3) issue_chunk(kc + 1, (kc + 1) & 1);
        if (kc < 3) cp_wait<1>(); else cp_wait<0>();
        __syncthreads();

        const uint32_t bufb = sb + (kc & 1) * BUF_B;
        const uint32_t aT = bufb + (wm * 64) * TS_ROWB + a_lane_off;
        const uint32_t bT = bufb + TILE_B + (wn * 32) * TS_ROWB + b_lane_off;

#pragma unroll
        for (int step = 0; step < 4; step++) {
            const uint32_t koff = step * 32;   // 16 fp16 = 32 bytes
            uint32_t bh[8];
            ldsm_x4(bh + 0, bT + koff);                       // n 0-15
            ldsm_x4(bh + 4, bT + 16 * TS_ROWB + koff);        // n 16-31
#pragma unroll
            for (int mi = 0; mi < 4; mi++) {
                uint32_t ah[4];
                ldsm_x4(ah, aT + mi * 16 * TS_ROWB + koff);
#pragma unroll
                for (int ni = 0; ni < 4; ni++)
                    mma_f16(acc[mi][ni], ah, bh + ni * 2);
            }
        }
        __syncthreads();
    }

    // ---- Epilogue: exp in regs -> smem stage (128 x 132 fp32) -> coalesced STG
    float* sout = reinterpret_cast<float*>(smem);
    const int r0 = lane >> 2;
    const int cpair = (lane & 3) * 2;
#pragma unroll
    for (int mi = 0; mi < 4; mi++) {
        const int lrow0 = wm * 64 + mi * 16 + r0;    // local row 0..127
        const int grow0 = mtile * 128 + lrow0;
        const float scl0 = g_scale[c * BB + grow0];
        const float scl1 = g_scale[c * BB + grow0 + 8];
#pragma unroll
        for (int ni = 0; ni < 4; ni++) {
            const int col = wn * 32 + ni * 8 + cpair;
            sout[lrow0 * EPI_STRIDE + col + 0]       = __expf(acc[mi][ni][0] * scl0);
            sout[lrow0 * EPI_STRIDE + col + 1]       = __expf(acc[mi][ni][1] * scl0);
            sout[(lrow0 + 8) * EPI_STRIDE + col + 0] = __expf(acc[mi][ni][2] * scl1);
            sout[(lrow0 + 8) * EPI_STRIDE + col + 1] = __expf(acc[mi][ni][3] * scl1);
        }
    }
    __syncthreads();

    // drain: warp writes 32 consecutive floats per instruction (coalesced)
    const size_t ocol = 1 + (size_t)ntile * 128;
#pragma unroll 8
    for (int it = 0; it < 64; it++) {
        int flat = it * 256 + tid;                 // 0..16383
        int row = flat >> 7;
        int col = flat & 127;
        float v = sout[row * EPI_STRIDE + col];
        int grow = mtile * 128 + row;
        out[((size_t)c * BB + grow) * ROWL + ocol + col] = v;
    }
}

// ----------------------------------------------------------------------------
// kernel_launch — input order detected from in_sizes (interleaved vs grouped)
// ----------------------------------------------------------------------------
extern "C" void kernel_launch(void* const* d_in, const int* in_sizes, int n_in,
                              void* d_out, int out_size) {
    (void)n_in; (void)out_size;
    const float* x[4]; const float* y[4]; const float* m[4];
    const bool interleaved = (in_sizes[2] == QQ * DD);
    for (int v = 0; v < 4; v++) {
        if (interleaved) {
            x[v] = (const float*)d_in[3 * v + 0];
            y[v] = (const float*)d_in[3 * v + 1];
            m[v] = (const float*)d_in[3 * v + 2];
        } else {
            x[v] = (const float*)d_in[v];
            y[v] = (const float*)d_in[4 + v];
            m[v] = (const float*)d_in[8 + v];
        }
    }
    float* out = (float*)d_out;
    float* out_mem = out + (size_t)NCOMBO * BB * ROWL;

    cudaFuncSetAttribute(k_gemm, cudaFuncAttributeMaxDynamicSharedMemorySize, GEMM_SMEM);

    k_prep_x<<<dim3(160, 4), 256>>>(x[0], x[1], x[2], x[3],
                                    y[0], y[1], y[2], y[3], out_mem);
    k_self<<<512, 256>>>(x[0], x[1], x[2], x[3], out);
    k_prep_mem<<<dim3(4096, 4), 256>>>(m[0], m[1], m[2], m[3]);
    k_gemm<<<dim3(32, 256), 256, GEMM_SMEM>>>(out, m[0], m[1], m[2], m[3], out_mem);
}